// round 3
// baseline (speedup 1.0000x reference)
#include <cuda_runtime.h>

#define NV 16384          // number of z vectors = 16*32*32
#define NE 16384          // codebook entries
#define DIM 256
#define HW 1024           // 32*32
#define CHW 262144        // 256*1024
#define OUT_ELEMS 4194304 // 16*256*32*32

#define BM 128
#define BN 128
#define BK 32

__device__ float g_z2[NV];
__device__ int   g_idx[NV];
__device__ float g_partial[512];

// ---------------------------------------------------------------------------
// z2[m] = sum_c z[b,c,p]^2  (m = b*1024 + p). One warp per row.
// ---------------------------------------------------------------------------
__global__ __launch_bounds__(256) void z2_kernel(const float* __restrict__ z) {
    int m = blockIdx.x * 8 + (threadIdx.x >> 5);
    int lane = threadIdx.x & 31;
    int b = m >> 10, p = m & 1023;
    const float* base = z + (size_t)b * CHW + p;
    float s = 0.f;
#pragma unroll
    for (int c = 0; c < DIM; c += 32) {
        float v = base[(size_t)(c + lane) * HW];
        s = fmaf(v, v, s);
    }
#pragma unroll
    for (int o = 16; o > 0; o >>= 1) s += __shfl_xor_sync(0xffffffffu, s, o);
    if (lane == 0) g_z2[m] = s;
}

// ---------------------------------------------------------------------------
// Fused GEMM + argmin: for each m, idx = argmin_n fl(z2[m] - 2*dot(z_m, e_n))
// with first-index tie-break (matches jnp.argmin on the fp32-rounded d; the
// |e|^2 term rounds away entirely at magnitude ~256).
// BM=128 x BN=128 tile, BK=32, 256 threads, 8x8 per thread. Grid = 128 blocks,
// each block scans all 16384 codebook entries with a running best.
// ---------------------------------------------------------------------------
__global__ __launch_bounds__(256, 1) void argmin_kernel(const float* __restrict__ z,
                                                        const float* __restrict__ cb) {
    __shared__ float As[BK][BM];
    __shared__ float Bs[BK][BN];

    const int tid = threadIdx.x;
    const int tx = tid & 15;   // 0..15  -> 8 n-cols each
    const int ty = tid >> 4;   // 0..15  -> 8 m-rows each
    const int m0 = blockIdx.x * BM;
    const int b  = m0 >> 10;
    const int p0 = m0 & 1023;
    const float* zbase = z + (size_t)b * CHW + p0;

    float az2[8];
#pragma unroll
    for (int i = 0; i < 8; i++) az2[i] = g_z2[m0 + ty * 8 + i];

    float best_d[8];
    int   best_n[8];
#pragma unroll
    for (int i = 0; i < 8; i++) { best_d[i] = 3.4e38f; best_n[i] = 0; }

    for (int n0 = 0; n0 < NE; n0 += BN) {
        float acc[8][8];
#pragma unroll
        for (int i = 0; i < 8; i++)
#pragma unroll
            for (int j = 0; j < 8; j++) acc[i][j] = 0.f;

        for (int k0 = 0; k0 < DIM; k0 += BK) {
            __syncthreads();
            // A tile: 128 m x 32 k, coalesced along m (contiguous p)
            {
                int lane = tid & 31;
                int kk0 = tid >> 5;
#pragma unroll
                for (int r = 0; r < 4; r++) {
                    int kk = kk0 + r * 8;
                    float4 v = *(const float4*)(zbase + (size_t)(k0 + kk) * HW + lane * 4);
                    *(float4*)&As[kk][lane * 4] = v;
                }
            }
            // B tile: 128 n x 32 k, transposed into Bs[k][n]
#pragma unroll
            for (int r = 0; r < 4; r++) {
                int s = r * 256 + tid;
                int n = s >> 3;
                int kq = (s & 7) * 4;
                float4 v = *(const float4*)(cb + (size_t)(n0 + n) * DIM + k0 + kq);
                Bs[kq + 0][n] = v.x;
                Bs[kq + 1][n] = v.y;
                Bs[kq + 2][n] = v.z;
                Bs[kq + 3][n] = v.w;
            }
            __syncthreads();
#pragma unroll
            for (int kk = 0; kk < BK; kk++) {
                float a[8], bb[8];
                *(float4*)&a[0]  = *(const float4*)&As[kk][ty * 8];
                *(float4*)&a[4]  = *(const float4*)&As[kk][ty * 8 + 4];
                *(float4*)&bb[0] = *(const float4*)&Bs[kk][tx * 8];
                *(float4*)&bb[4] = *(const float4*)&Bs[kk][tx * 8 + 4];
#pragma unroll
                for (int i = 0; i < 8; i++)
#pragma unroll
                    for (int j = 0; j < 8; j++)
                        acc[i][j] = fmaf(a[i], bb[j], acc[i][j]);
            }
        }

        // Epilogue: d = fl(z2 - 2*dot) (single-rounding FMA, matches reference),
        // tie-aware running min (lowest n wins on exact equality).
#pragma unroll
        for (int i = 0; i < 8; i++) {
            float bd = best_d[i]; int bn = best_n[i];
#pragma unroll
            for (int j = 0; j < 8; j++) {
                int n = n0 + tx * 8 + j;
                float d = fmaf(-2.f, acc[i][j], az2[i]);
                if (d < bd || (d == bd && n < bn)) { bd = d; bn = n; }
            }
#pragma unroll
            for (int o = 1; o < 16; o <<= 1) {
                float od = __shfl_xor_sync(0xffffffffu, bd, o);
                int   on = __shfl_xor_sync(0xffffffffu, bn, o);
                if (od < bd || (od == bd && on < bn)) { bd = od; bn = on; }
            }
            best_d[i] = bd; best_n[i] = bn;
        }
    }

    if (tx == 0) {
#pragma unroll
        for (int i = 0; i < 8; i++) g_idx[m0 + ty * 8 + i] = best_n[i];
    }
}

// ---------------------------------------------------------------------------
// Gather z_q = codebook[idx], write out[b,c,h,w] = fl(z + fl(zq - z))
// (straight-through rounding replicated exactly), accumulate loss partials,
// and emit idx as float. One block = 32 consecutive m rows.
// ---------------------------------------------------------------------------
__global__ __launch_bounds__(256) void outloss_kernel(const float* __restrict__ z,
                                                      const float* __restrict__ cb,
                                                      float* __restrict__ dout) {
    __shared__ float s_zq[32][257];
    __shared__ int   s_idx[32];
    __shared__ float s_red[8];
    const int tid = threadIdx.x;
    const int m0 = blockIdx.x * 32;
    const int b  = m0 >> 10;
    const int p0 = m0 & 1023;

    if (tid < 32) s_idx[tid] = g_idx[m0 + tid];
    __syncthreads();

    const int w = tid >> 5, lane = tid & 31;
    for (int r = w; r < 32; r += 8) {
        const float* row = cb + (size_t)s_idx[r] * DIM;
        for (int c = lane; c < DIM; c += 32) s_zq[r][c] = row[c];
    }
    __syncthreads();

    const float* zb = z + (size_t)b * CHW + p0;
    float* ob = dout + (size_t)b * CHW + p0;
    float lsum = 0.f;
#pragma unroll 4
    for (int i = 0; i < 32; i++) {
        int c = i * 8 + w;
        float q  = s_zq[lane][c];
        float zv = zb[(size_t)c * HW + lane];
        float t  = q - zv;              // fl(zq - z)
        lsum = fmaf(t, t, lsum);
        ob[(size_t)c * HW + lane] = zv + t;   // fl(z + t): straight-through value
    }

    if (tid < 32) dout[OUT_ELEMS + 1 + m0 + tid] = (float)s_idx[tid];

#pragma unroll
    for (int o = 16; o > 0; o >>= 1) lsum += __shfl_xor_sync(0xffffffffu, lsum, o);
    if (lane == 0) s_red[w] = lsum;
    __syncthreads();
    if (tid == 0) {
        float t = 0.f;
#pragma unroll
        for (int k = 0; k < 8; k++) t += s_red[k];
        g_partial[blockIdx.x] = t;
    }
}

// ---------------------------------------------------------------------------
// Final deterministic loss reduce: loss = m + 0.25*m, m = sum/4194304
// ---------------------------------------------------------------------------
__global__ __launch_bounds__(256) void final_kernel(float* __restrict__ dout) {
    __shared__ float s_red[8];
    int tid = threadIdx.x;
    float s = g_partial[tid] + g_partial[tid + 256];
#pragma unroll
    for (int o = 16; o > 0; o >>= 1) s += __shfl_xor_sync(0xffffffffu, s, o);
    if ((tid & 31) == 0) s_red[tid >> 5] = s;
    __syncthreads();
    if (tid == 0) {
        float t = 0.f;
#pragma unroll
        for (int k = 0; k < 8; k++) t += s_red[k];
        float m = t / (float)OUT_ELEMS;
        dout[OUT_ELEMS] = m + 0.25f * m;
    }
}

extern "C" void kernel_launch(void* const* d_in, const int* in_sizes, int n_in,
                              void* d_out, int out_size) {
    const float* z  = (const float*)d_in[0];
    const float* cb = (const float*)d_in[1];
    float* out = (float*)d_out;
    (void)in_sizes; (void)n_in; (void)out_size;

    z2_kernel<<<NV / 8, 256>>>(z);
    argmin_kernel<<<NV / BM, 256>>>(z, cb);
    outloss_kernel<<<NV / 32, 256>>>(z, cb, out);
    final_kernel<<<1, 256>>>(out);
}